// round 2
// baseline (speedup 1.0000x reference)
#include <cuda_runtime.h>
#include <cstdint>

#define BATCH   4
#define NSEQ    2048
#define DIM     1024
#define QK_DIM  1024
#define V_DIM   1024
#define HEADS   16
#define DHEAD   64           // QK_DIM/HEADS == V_DIM/HEADS
#define KVW     (QK_DIM + V_DIM)   // 2048

// Scratch (allocation-free rule: __device__ globals)
__device__ float g_q [ (size_t)BATCH * NSEQ * QK_DIM ];   // 32 MB
__device__ float g_kv[ (size_t)BATCH * NSEQ * KVW    ];   // 64 MB

// ---------------------------------------------------------------------------
// Tiled fp32 GEMM: C[M,N] = A[M,K] @ B[K,N], all row-major.
// 128x128 block, BK=16, 256 threads, 8x8 micro-tile per thread.
// ---------------------------------------------------------------------------
__global__ __launch_bounds__(256) void gemm128(const float* __restrict__ A,
                                               const float* __restrict__ Bm,
                                               float* __restrict__ C,
                                               int M, int N, int K) {
    __shared__ __align__(16) float As[16][128];   // [k][m]
    __shared__ __align__(16) float Bs[16][128];   // [k][n]

    const int tid = threadIdx.x;
    const int ty  = tid >> 4;       // 0..15
    const int tx  = tid & 15;       // 0..15
    const int rowBase = blockIdx.y * 128;
    const int colBase = blockIdx.x * 128;

    float acc[8][8];
#pragma unroll
    for (int r = 0; r < 8; r++)
#pragma unroll
        for (int c = 0; c < 8; c++) acc[r][c] = 0.f;

    for (int k0 = 0; k0 < K; k0 += 16) {
        // A tile 128x16 -> As[k][m] (transposed store)
#pragma unroll
        for (int i = 0; i < 2; i++) {
            int lidx = tid + i * 256;          // 0..511
            int ar   = lidx >> 2;              // 0..127
            int ac   = (lidx & 3) << 2;        // 0,4,8,12
            float4 v = *reinterpret_cast<const float4*>(
                &A[(size_t)(rowBase + ar) * K + k0 + ac]);
            As[ac + 0][ar] = v.x;
            As[ac + 1][ar] = v.y;
            As[ac + 2][ar] = v.z;
            As[ac + 3][ar] = v.w;
        }
        // B tile 16x128 -> Bs[k][n] (direct float4)
#pragma unroll
        for (int i = 0; i < 2; i++) {
            int lidx = tid + i * 256;
            int br   = lidx >> 5;              // 0..15
            int bc   = (lidx & 31) << 2;       // 0..124
            *reinterpret_cast<float4*>(&Bs[br][bc]) =
                *reinterpret_cast<const float4*>(
                    &Bm[(size_t)(k0 + br) * N + colBase + bc]);
        }
        __syncthreads();

#pragma unroll
        for (int kk = 0; kk < 16; kk++) {
            float a[8], b[8];
            *reinterpret_cast<float4*>(a)     = *reinterpret_cast<float4*>(&As[kk][ty * 8]);
            *reinterpret_cast<float4*>(a + 4) = *reinterpret_cast<float4*>(&As[kk][ty * 8 + 4]);
            *reinterpret_cast<float4*>(b)     = *reinterpret_cast<float4*>(&Bs[kk][tx * 8]);
            *reinterpret_cast<float4*>(b + 4) = *reinterpret_cast<float4*>(&Bs[kk][tx * 8 + 4]);
#pragma unroll
            for (int r = 0; r < 8; r++)
#pragma unroll
                for (int c = 0; c < 8; c++)
                    acc[r][c] += a[r] * b[c];
        }
        __syncthreads();
    }

#pragma unroll
    for (int r = 0; r < 8; r++) {
        size_t base = (size_t)(rowBase + ty * 8 + r) * N + colBase + tx * 8;
        float4 v0 = make_float4(acc[r][0], acc[r][1], acc[r][2], acc[r][3]);
        float4 v1 = make_float4(acc[r][4], acc[r][5], acc[r][6], acc[r][7]);
        *reinterpret_cast<float4*>(&C[base])     = v0;
        *reinterpret_cast<float4*>(&C[base + 4]) = v1;
    }
}

// ---------------------------------------------------------------------------
// Flash attention (fp32, online softmax).
// One CTA per (b, h, 64-row Q tile). KV processed in 32-row tiles.
// 256 threads. O micro-tile 4x4 per thread; S micro-tile 4x2.
// ---------------------------------------------------------------------------
__global__ __launch_bounds__(256) void attn64(const float* __restrict__ q,
                                              const float* __restrict__ kv,
                                              float* __restrict__ out) {
    __shared__ __align__(16) float Qts[64][68];   // [k][i], padded
    __shared__ __align__(16) float Kts[64][34];   // [k][j]
    __shared__ __align__(16) float Vs [32][64];   // [j][d]
    __shared__ __align__(16) float Pts[32][68];   // [j][i]  (i spans 64 q rows + pad)
    __shared__ float rowm[64], rowl[64], alp[64];

    const int tid = threadIdx.x;
    const int ty  = tid >> 4;       // 0..15
    const int tx  = tid & 15;       // 0..15
    const int qt  = blockIdx.x;     // 0..31
    const int h   = blockIdx.y;     // 0..15
    const int b   = blockIdx.z;     // 0..3

    const float* qp = q  + ((size_t)b * NSEQ + qt * 64) * QK_DIM + h * DHEAD;
    const float* kp = kv + (size_t)b * NSEQ * KVW + h * DHEAD;
    const float* vp = kp + QK_DIM;

    // Load Q tile 64x64 -> Qts[k][i]
#pragma unroll
    for (int i = 0; i < 4; i++) {
        int lidx = tid + i * 256;           // 0..1023
        int r    = lidx >> 4;               // 0..63 (q row)
        int k4   = (lidx & 15) << 2;        // 0..60
        float4 v = *reinterpret_cast<const float4*>(&qp[(size_t)r * QK_DIM + k4]);
        Qts[k4 + 0][r] = v.x;
        Qts[k4 + 1][r] = v.y;
        Qts[k4 + 2][r] = v.z;
        Qts[k4 + 3][r] = v.w;
    }
    if (tid < 64) { rowm[tid] = -1e30f; rowl[tid] = 0.f; }

    float o[4][4];
#pragma unroll
    for (int r = 0; r < 4; r++)
#pragma unroll
        for (int c = 0; c < 4; c++) o[r][c] = 0.f;

    const float scale = 0.125f;   // 64^-0.5
    const int i0 = ty * 4;        // q-row base of this thread
    const int j0 = tx * 2;        // kv-col base (S phase)
    const int d0 = tx * 4;        // head-dim base (O phase)

    for (int jt = 0; jt < NSEQ / 32; jt++) {
        __syncthreads();   // previous-tile consumers done; Q visible on first pass

        // Load K tile 32x64 -> Kts[k][j], V tile 32x64 -> Vs[j][d]
#pragma unroll
        for (int i = 0; i < 2; i++) {
            int lidx = tid + i * 256;        // 0..511
            int r    = lidx >> 4;            // 0..31
            int k4   = (lidx & 15) << 2;
            float4 v = *reinterpret_cast<const float4*>(
                &kp[((size_t)(jt * 32 + r)) * KVW + k4]);
            Kts[k4 + 0][r] = v.x;
            Kts[k4 + 1][r] = v.y;
            Kts[k4 + 2][r] = v.z;
            Kts[k4 + 3][r] = v.w;
        }
#pragma unroll
        for (int i = 0; i < 2; i++) {
            int lidx = tid + i * 256;
            int r    = lidx >> 4;
            int d4   = (lidx & 15) << 2;
            *reinterpret_cast<float4*>(&Vs[r][d4]) =
                *reinterpret_cast<const float4*>(
                    &vp[((size_t)(jt * 32 + r)) * KVW + d4]);
        }
        __syncthreads();

        // S = scale * Q @ K^T  (4x2 per thread)
        float s[4][2];
#pragma unroll
        for (int r = 0; r < 4; r++) { s[r][0] = 0.f; s[r][1] = 0.f; }
#pragma unroll
        for (int k = 0; k < 64; k++) {
            float a[4], bb[2];
            *reinterpret_cast<float4*>(a)  = *reinterpret_cast<float4*>(&Qts[k][i0]);
            *reinterpret_cast<float2*>(bb) = *reinterpret_cast<float2*>(&Kts[k][j0]);
#pragma unroll
            for (int r = 0; r < 4; r++) {
                s[r][0] += a[r] * bb[0];
                s[r][1] += a[r] * bb[1];
            }
        }
#pragma unroll
        for (int c = 0; c < 2; c++) {
            float4 v = make_float4(s[0][c] * scale, s[1][c] * scale,
                                   s[2][c] * scale, s[3][c] * scale);
            *reinterpret_cast<float4*>(&Pts[j0 + c][i0]) = v;
        }
        __syncthreads();

        // Online softmax: thread i owns row i
        if (tid < 64) {
            int i = tid;
            float m  = rowm[i];
            float mn = m;
#pragma unroll
            for (int j = 0; j < 32; j++) mn = fmaxf(mn, Pts[j][i]);
            float a = __expf(m - mn);
            float l = rowl[i] * a;
#pragma unroll
            for (int j = 0; j < 32; j++) {
                float p = __expf(Pts[j][i] - mn);
                Pts[j][i] = p;
                l += p;
            }
            rowm[i] = mn; rowl[i] = l; alp[i] = a;
        }
        __syncthreads();

        // O = O*alpha + P @ V
        float av[4];
#pragma unroll
        for (int r = 0; r < 4; r++) av[r] = alp[i0 + r];
#pragma unroll
        for (int r = 0; r < 4; r++)
#pragma unroll
            for (int c = 0; c < 4; c++) o[r][c] *= av[r];

#pragma unroll
        for (int j = 0; j < 32; j++) {
            float p[4], v[4];
            *reinterpret_cast<float4*>(p) = *reinterpret_cast<float4*>(&Pts[j][i0]);
            *reinterpret_cast<float4*>(v) = *reinterpret_cast<float4*>(&Vs[j][d0]);
#pragma unroll
            for (int r = 0; r < 4; r++)
#pragma unroll
                for (int c = 0; c < 4; c++)
                    o[r][c] += p[r] * v[c];
        }
    }

    // Epilogue: normalize and store
    float inv[4];
#pragma unroll
    for (int r = 0; r < 4; r++) inv[r] = 1.f / rowl[i0 + r];

#pragma unroll
    for (int r = 0; r < 4; r++) {
        size_t base = ((size_t)b * NSEQ + qt * 64 + i0 + r) * (HEADS * DHEAD)
                    + h * DHEAD + d0;
        float4 v = make_float4(o[r][0] * inv[r], o[r][1] * inv[r],
                               o[r][2] * inv[r], o[r][3] * inv[r]);
        *reinterpret_cast<float4*>(&out[base]) = v;
    }
}

// ---------------------------------------------------------------------------
extern "C" void kernel_launch(void* const* d_in, const int* in_sizes, int n_in,
                              void* d_out, int out_size) {
    const float* x   = (const float*)d_in[0];   // [4,2048,1024]
    const float* ctx = (const float*)d_in[1];   // [4,2048,1024]
    const float* Wq  = (const float*)d_in[2];   // [1024,1024]
    const float* Wkv = (const float*)d_in[3];   // [1024,2048]
    // Disambiguate Wq/Wkv by size in case of metadata reordering
    if (n_in >= 4 && in_sizes[2] == QK_DIM * KVW && in_sizes[3] == DIM * QK_DIM) {
        const float* t = Wq; Wq = Wkv; Wkv = t;
    }
    float* out = (float*)d_out;

    void* qptr  = nullptr;
    void* kvptr = nullptr;
    cudaGetSymbolAddress(&qptr,  g_q);
    cudaGetSymbolAddress(&kvptr, g_kv);
    float* q  = (float*)qptr;
    float* kv = (float*)kvptr;

    const int M = BATCH * NSEQ;   // 8192

    // Q = x @ Wq          [8192,1024] x [1024,1024]
    gemm128<<<dim3(QK_DIM / 128, M / 128), 256>>>(x, Wq, q, M, QK_DIM, DIM);
    // KV = context @ Wkv  [8192,1024] x [1024,2048]
    gemm128<<<dim3(KVW / 128, M / 128), 256>>>(ctx, Wkv, kv, M, KVW, DIM);
    // Attention
    attn64<<<dim3(NSEQ / 64, HEADS, BATCH), 256>>>(q, kv, out);
}

// round 4
// speedup vs baseline: 1.3198x; 1.3198x over previous
#include <cuda_runtime.h>
#include <cuda_bf16.h>
#include <cstdint>

#define BATCH   4
#define NSEQ    2048
#define DIM     1024
#define QK_DIM  1024
#define V_DIM   1024
#define HEADS   16
#define DHEAD   64
#define KVW     (QK_DIM + V_DIM)   // 2048
#define MROWS   (BATCH * NSEQ)     // 8192

// ---------------- scratch (__device__ globals; no allocs allowed) ----------
__device__ float g_q [ (size_t)MROWS * QK_DIM ];
__device__ float g_kv[ (size_t)MROWS * KVW    ];
__device__ __nv_bfloat16 g_xh[ (size_t)MROWS * DIM ];
__device__ __nv_bfloat16 g_xl[ (size_t)MROWS * DIM ];
__device__ __nv_bfloat16 g_ch[ (size_t)MROWS * DIM ];
__device__ __nv_bfloat16 g_cl[ (size_t)MROWS * DIM ];
__device__ __nv_bfloat16 g_wqh[ (size_t)QK_DIM * DIM ];   // [N,K]
__device__ __nv_bfloat16 g_wql[ (size_t)QK_DIM * DIM ];
__device__ __nv_bfloat16 g_wkh[ (size_t)KVW * DIM ];      // [N,K]
__device__ __nv_bfloat16 g_wkl[ (size_t)KVW * DIM ];

// ---------------- small PTX helpers (all baseline sm_80+, no 'a' features) --
__device__ __forceinline__ uint32_t smem_u32(const void* p) {
    uint32_t a;
    asm("{ .reg .u64 t; cvta.to.shared.u64 t, %1; cvt.u32.u64 %0, t; }"
        : "=r"(a) : "l"(p));
    return a;
}
__device__ __forceinline__ void cp_async16(uint32_t sdst, const void* gsrc) {
    asm volatile("cp.async.cg.shared.global [%0], [%1], 16;"
                 :: "r"(sdst), "l"(gsrc) : "memory");
}
#define CP_COMMIT() asm volatile("cp.async.commit_group;" ::: "memory")
#define CP_WAIT(N)  asm volatile("cp.async.wait_group %0;" :: "n"(N) : "memory")

__device__ __forceinline__ void ldsm4(uint32_t* r, uint32_t addr) {
    asm volatile("ldmatrix.sync.aligned.m8n8.x4.shared.b16 {%0,%1,%2,%3}, [%4];"
                 : "=r"(r[0]), "=r"(r[1]), "=r"(r[2]), "=r"(r[3]) : "r"(addr));
}
__device__ __forceinline__ void mma16816(float* c, const uint32_t* a,
                                         uint32_t b0, uint32_t b1) {
    asm volatile(
        "mma.sync.aligned.m16n8k16.row.col.f32.bf16.bf16.f32 "
        "{%0,%1,%2,%3}, {%4,%5,%6,%7}, {%8,%9}, {%0,%1,%2,%3};"
        : "+f"(c[0]), "+f"(c[1]), "+f"(c[2]), "+f"(c[3])
        : "r"(a[0]), "r"(a[1]), "r"(a[2]), "r"(a[3]), "r"(b0), "r"(b1));
}

// ---------------- prep: split fp32 -> bf16 hi/lo ----------------------------
__device__ __forceinline__ void split1(float x, __nv_bfloat16& h, __nv_bfloat16& l) {
    h = __float2bfloat16(x);
    l = __float2bfloat16(x - __bfloat162float(h));
}

__global__ __launch_bounds__(256) void asplit(const float* __restrict__ X,
                                              __nv_bfloat16* __restrict__ hi,
                                              __nv_bfloat16* __restrict__ lo,
                                              int n) {
    int i = (blockIdx.x * 256 + threadIdx.x) * 4;
    if (i >= n) return;
    float4 v = *reinterpret_cast<const float4*>(X + i);
    __nv_bfloat16 h[4], l[4];
    split1(v.x, h[0], l[0]); split1(v.y, h[1], l[1]);
    split1(v.z, h[2], l[2]); split1(v.w, h[3], l[3]);
    *reinterpret_cast<uint2*>(hi + i) = *reinterpret_cast<uint2*>(h);
    *reinterpret_cast<uint2*>(lo + i) = *reinterpret_cast<uint2*>(l);
}

// W [K,N] f32 -> hi/lo [N,K] bf16 (transpose + split)
__global__ void wsplit(const float* __restrict__ W,
                       __nv_bfloat16* __restrict__ hi,
                       __nv_bfloat16* __restrict__ lo,
                       int Kd, int Nd) {
    __shared__ float t[32][33];
    int n0 = blockIdx.x * 32, k0 = blockIdx.y * 32;
    int tx = threadIdx.x, ty = threadIdx.y;    // (32, 8)
#pragma unroll
    for (int i = 0; i < 32; i += 8)
        t[ty + i][tx] = W[(size_t)(k0 + ty + i) * Nd + n0 + tx];
    __syncthreads();
#pragma unroll
    for (int i = 0; i < 32; i += 8) {
        float v = t[tx][ty + i];
        __nv_bfloat16 h, l; split1(v, h, l);
        hi[(size_t)(n0 + ty + i) * Kd + k0 + tx] = h;
        lo[(size_t)(n0 + ty + i) * Kd + k0 + tx] = l;
    }
}

// ---------------- HMMA GEMM: C[M,N] = A[M,K] @ B[N,K]^T ---------------------
// bf16 hi/lo 3-product emulation. CTA tile 128x128, BK=64, 8 warps (warp tile
// 32x64), mma.sync m16n8k16, SW128-swizzled SMEM + ldmatrix, 2-stage cp.async.
#define BK 64
#define TILE_B (128 * 128)                 // one tile: 128 rows x 128 bytes
#define STAGE_B (4 * TILE_B)               // Ahi,Alo,Bhi,Blo
#define GEMM_SMEM (2 * STAGE_B)            // double buffered = 131072

__global__ __launch_bounds__(256, 1) void gemm_mma(
        const __nv_bfloat16* __restrict__ Ahi,
        const __nv_bfloat16* __restrict__ Alo,
        const __nv_bfloat16* __restrict__ Bhi,
        const __nv_bfloat16* __restrict__ Blo,
        float* __restrict__ C, int M, int N, int K) {
    extern __shared__ __align__(1024) char dsm[];
    const uint32_t sbase = smem_u32(dsm);

    const int tid  = threadIdx.x;
    const int wid  = tid >> 5;
    const int lane = tid & 31;
    const int wm   = wid & 3;        // 4 warps along M
    const int wn   = wid >> 2;       // 2 warps along N
    const int rowBase = blockIdx.y * 128;
    const int colBase = blockIdx.x * 128;

    const __nv_bfloat16* gsrc[4] = {
        Ahi + (size_t)rowBase * K, Alo + (size_t)rowBase * K,
        Bhi + (size_t)colBase * K, Blo + (size_t)colBase * K };

    // ---- stage loader (cp.async, SW128 swizzle) ----
    auto stage = [&](int kt, int buf) {
        const uint32_t sb = sbase + buf * STAGE_B;
#pragma unroll
        for (int t = 0; t < 4; t++) {
            const __nv_bfloat16* gp = gsrc[t] + kt * BK;
            const uint32_t stile = sb + t * TILE_B;
#pragma unroll
            for (int i = 0; i < 4; i++) {
                int idx = tid + i * 256;          // 0..1023
                int r   = idx >> 3;               // 0..127
                int c   = idx & 7;                // 16B chunk
                uint32_t so = (uint32_t)(r * 128 + ((c * 16) ^ ((r & 7) << 4)));
                cp_async16(stile + so, gp + (size_t)r * K + c * 8);
            }
        }
        CP_COMMIT();
    };

    // ---- per-lane ldmatrix address components ----
    // A fragment (m16k16 at m0,k0): lanes 0-15 -> rows m0+(l&15), k-half = l>>4
    int arow[2], axor[2];
#pragma unroll
    for (int mt = 0; mt < 2; mt++) {
        int row = wm * 32 + mt * 16 + (lane & 15);
        arow[mt] = row * 128;
        axor[mt] = (row & 7) << 4;
    }
    const int acolh = (lane >> 4) * 16;   // byte offset of k-half
    // B fragment pair (two n8 tiles x two k-halves per x4):
    // lanes: 0-7 (n0,k0) 8-15 (n0,k0+8) 16-23 (n0+8,k0) 24-31 (n0+8,k0+8)
    int brow[4], bxor[4];
#pragma unroll
    for (int nn = 0; nn < 4; nn++) {
        int row = wn * 64 + nn * 16 + (lane & 7) + ((lane >> 4) << 3);
        brow[nn] = row * 128;
        bxor[nn] = (row & 7) << 4;
    }
    const int bcolh = ((lane >> 3) & 1) * 16;

    float acc[2][8][4];
#pragma unroll
    for (int mt = 0; mt < 2; mt++)
#pragma unroll
        for (int nt = 0; nt < 8; nt++)
#pragma unroll
            for (int i = 0; i < 4; i++) acc[mt][nt][i] = 0.f;

    const int KT = K / BK;
    stage(0, 0);

    for (int kt = 0; kt < KT; kt++) {
        if (kt + 1 < KT) { stage(kt + 1, (kt + 1) & 1); CP_WAIT(1); }
        else             { CP_WAIT(0); }
        __syncthreads();

        const uint32_t sb   = sbase + (kt & 1) * STAGE_B;
        const uint32_t sAhi = sb;
        const uint32_t sAlo = sb + TILE_B;
        const uint32_t sBhi = sb + 2 * TILE_B;
        const uint32_t sBlo = sb + 3 * TILE_B;

#pragma unroll
        for (int kk = 0; kk < 4; kk++) {          // 4 x k16 per BK=64
            const int kb = kk * 32;               // byte offset of k0
            uint32_t ah[2][4], al[2][4], bh[4][4], bl[4][4];
#pragma unroll
            for (int mt = 0; mt < 2; mt++) {
                uint32_t off = (uint32_t)(arow[mt] + ((kb + acolh) ^ axor[mt]));
                ldsm4(ah[mt], sAhi + off);
                ldsm4(al[mt], sAlo + off);
            }
#pragma unroll
            for (int nn = 0; nn < 4; nn++) {
                uint32_t off = (uint32_t)(brow[nn] + ((kb + bcolh) ^ bxor[nn]));
                ldsm4(bh[nn], sBhi + off);
                ldsm4(bl[nn], sBlo + off);
            }
#pragma unroll
            for (int mt = 0; mt < 2; mt++)
#pragma unroll
                for (int nt = 0; nt < 8; nt++) {
                    const int nn = nt >> 1, hf = (nt & 1) * 2;
                    mma16816(acc[mt][nt], ah[mt], bh[nn][hf], bh[nn][hf + 1]);
                    mma16816(acc[mt][nt], ah[mt], bl[nn][hf], bl[nn][hf + 1]);
                    mma16816(acc[mt][nt], al[mt], bh[nn][hf], bh[nn][hf + 1]);
                }
        }
        __syncthreads();
    }

    // ---- epilogue: c0,c1 -> (row g, col 2t..2t+1); c2,c3 -> (row g+8) ----
    const int g   = lane >> 2;
    const int tig = lane & 3;
#pragma unroll
    for (int mt = 0; mt < 2; mt++) {
        const int row0 = rowBase + wm * 32 + mt * 16 + g;
#pragma unroll
        for (int nt = 0; nt < 8; nt++) {
            const int col = colBase + wn * 64 + nt * 8 + tig * 2;
            *reinterpret_cast<float2*>(&C[(size_t)row0 * N + col]) =
                make_float2(acc[mt][nt][0], acc[mt][nt][1]);
            *reinterpret_cast<float2*>(&C[(size_t)(row0 + 8) * N + col]) =
                make_float2(acc[mt][nt][2], acc[mt][nt][3]);
        }
    }
}

// ---------------- flash attention (fp32, unchanged) -------------------------
__global__ __launch_bounds__(256) void attn64(const float* __restrict__ q,
                                              const float* __restrict__ kv,
                                              float* __restrict__ out) {
    __shared__ __align__(16) float Qts[64][68];
    __shared__ __align__(16) float Kts[64][34];
    __shared__ __align__(16) float Vs [32][64];
    __shared__ __align__(16) float Pts[32][68];
    __shared__ float rowm[64], rowl[64], alp[64];

    const int tid = threadIdx.x;
    const int ty  = tid >> 4;
    const int tx  = tid & 15;
    const int qt  = blockIdx.x;
    const int h   = blockIdx.y;
    const int b   = blockIdx.z;

    const float* qp = q  + ((size_t)b * NSEQ + qt * 64) * QK_DIM + h * DHEAD;
    const float* kp = kv + (size_t)b * NSEQ * KVW + h * DHEAD;
    const float* vp = kp + QK_DIM;

#pragma unroll
    for (int i = 0; i < 4; i++) {
        int lidx = tid + i * 256;
        int r    = lidx >> 4;
        int k4   = (lidx & 15) << 2;
        float4 v = *reinterpret_cast<const float4*>(&qp[(size_t)r * QK_DIM + k4]);
        Qts[k4 + 0][r] = v.x; Qts[k4 + 1][r] = v.y;
        Qts[k4 + 2][r] = v.z; Qts[k4 + 3][r] = v.w;
    }
    if (tid < 64) { rowm[tid] = -1e30f; rowl[tid] = 0.f; }

    float o[4][4];
#pragma unroll
    for (int r = 0; r < 4; r++)
#pragma unroll
        for (int c = 0; c < 4; c++) o[r][c] = 0.f;

    const float scale = 0.125f;
    const int i0 = ty * 4;
    const int j0 = tx * 2;
    const int d0 = tx * 4;

    for (int jt = 0; jt < NSEQ / 32; jt++) {
        __syncthreads();
#pragma unroll
        for (int i = 0; i < 2; i++) {
            int lidx = tid + i * 256;
            int r    = lidx >> 4;
            int k4   = (lidx & 15) << 2;
            float4 v = *reinterpret_cast<const float4*>(
                &kp[((size_t)(jt * 32 + r)) * KVW + k4]);
            Kts[k4 + 0][r] = v.x; Kts[k4 + 1][r] = v.y;
            Kts[k4 + 2][r] = v.z; Kts[k4 + 3][r] = v.w;
        }
#pragma unroll
        for (int i = 0; i < 2; i++) {
            int lidx = tid + i * 256;
            int r    = lidx >> 4;
            int d4   = (lidx & 15) << 2;
            *reinterpret_cast<float4*>(&Vs[r][d4]) =
                *reinterpret_cast<const float4*>(
                    &vp[((size_t)(jt * 32 + r)) * KVW + d4]);
        }
        __syncthreads();

        float s[4][2];
#pragma unroll
        for (int r = 0; r < 4; r++) { s[r][0] = 0.f; s[r][1] = 0.f; }
#pragma unroll
        for (int k = 0; k < 64; k++) {
            float a[4], bb[2];
            *reinterpret_cast<float4*>(a)  = *reinterpret_cast<float4*>(&Qts[k][i0]);
            *reinterpret_cast<float2*>(bb) = *reinterpret_cast<float2*>(&Kts[k][j0]);
#pragma unroll
            for (int r = 0; r < 4; r++) {
                s[r][0] += a[r] * bb[0];
                s[r][1] += a[r] * bb[1];
            }
        }
#pragma unroll
        for (int c = 0; c < 2; c++) {
            float4 v = make_float4(s[0][c] * scale, s[1][c] * scale,
                                   s[2][c] * scale, s[3][c] * scale);
            *reinterpret_cast<float4*>(&Pts[j0 + c][i0]) = v;
        }
        __syncthreads();

        if (tid < 64) {
            int i = tid;
            float m  = rowm[i];
            float mn = m;
#pragma unroll
            for (int j = 0; j < 32; j++) mn = fmaxf(mn, Pts[j][i]);
            float a = __expf(m - mn);
            float l = rowl[i] * a;
#pragma unroll
            for (int j = 0; j < 32; j++) {
                float p = __expf(Pts[j][i] - mn);
                Pts[j][i] = p;
                l += p;
            }
            rowm[i] = mn; rowl[i] = l; alp[i] = a;
        }
        __syncthreads();

        float av[4];
#pragma unroll
        for (int r = 0; r < 4; r++) av[r] = alp[i0 + r];
#pragma unroll
        for (int r = 0; r < 4; r++)
#pragma unroll
            for (int c = 0; c < 4; c++) o[r][c] *= av[r];

#pragma unroll
        for (int j = 0; j < 32; j++) {
            float p[4], v[4];
            *reinterpret_cast<float4*>(p) = *reinterpret_cast<float4*>(&Pts[j][i0]);
            *reinterpret_cast<float4*>(v) = *reinterpret_cast<float4*>(&Vs[j][d0]);
#pragma unroll
            for (int r = 0; r < 4; r++)
#pragma unroll
                for (int c = 0; c < 4; c++)
                    o[r][c] += p[r] * v[c];
        }
    }

    float inv[4];
#pragma unroll
    for (int r = 0; r < 4; r++) inv[r] = 1.f / rowl[i0 + r];

#pragma unroll
    for (int r = 0; r < 4; r++) {
        size_t base = ((size_t)b * NSEQ + qt * 64 + i0 + r) * (HEADS * DHEAD)
                    + h * DHEAD + d0;
        float4 v = make_float4(o[r][0] * inv[r], o[r][1] * inv[r],
                               o[r][2] * inv[r], o[r][3] * inv[r]);
        *reinterpret_cast<float4*>(&out[base]) = v;
    }
}

// ---------------------------------------------------------------------------
extern "C" void kernel_launch(void* const* d_in, const int* in_sizes, int n_in,
                              void* d_out, int out_size) {
    const float* x   = (const float*)d_in[0];
    const float* ctx = (const float*)d_in[1];
    const float* Wq  = (const float*)d_in[2];
    const float* Wkv = (const float*)d_in[3];
    if (n_in >= 4 && in_sizes[2] == QK_DIM * KVW && in_sizes[3] == DIM * QK_DIM) {
        const float* t = Wq; Wq = Wkv; Wkv = t;
    }
    float* out = (float*)d_out;

    void *qp, *kvp, *xh, *xl, *ch, *cl, *wqh, *wql, *wkh, *wkl;
    cudaGetSymbolAddress(&qp,  g_q);   cudaGetSymbolAddress(&kvp, g_kv);
    cudaGetSymbolAddress(&xh,  g_xh);  cudaGetSymbolAddress(&xl,  g_xl);
    cudaGetSymbolAddress(&ch,  g_ch);  cudaGetSymbolAddress(&cl,  g_cl);
    cudaGetSymbolAddress(&wqh, g_wqh); cudaGetSymbolAddress(&wql, g_wql);
    cudaGetSymbolAddress(&wkh, g_wkh); cudaGetSymbolAddress(&wkl, g_wkl);

    cudaFuncSetAttribute(gemm_mma, cudaFuncAttributeMaxDynamicSharedMemorySize,
                         GEMM_SMEM);

    const int M = MROWS;
    const int nAct = M * DIM;

    asplit<<<nAct / (256 * 4), 256>>>(x,   (__nv_bfloat16*)xh, (__nv_bfloat16*)xl, nAct);
    asplit<<<nAct / (256 * 4), 256>>>(ctx, (__nv_bfloat16*)ch, (__nv_bfloat16*)cl, nAct);
    wsplit<<<dim3(QK_DIM / 32, DIM / 32), dim3(32, 8)>>>(
        Wq, (__nv_bfloat16*)wqh, (__nv_bfloat16*)wql, DIM, QK_DIM);
    wsplit<<<dim3(KVW / 32, DIM / 32), dim3(32, 8)>>>(
        Wkv, (__nv_bfloat16*)wkh, (__nv_bfloat16*)wkl, DIM, KVW);

    // Q = x @ Wq  (HMMA bf16 hi/lo 3-product)
    gemm_mma<<<dim3(QK_DIM / 128, M / 128), 256, GEMM_SMEM>>>(
        (const __nv_bfloat16*)xh, (const __nv_bfloat16*)xl,
        (const __nv_bfloat16*)wqh, (const __nv_bfloat16*)wql,
        (float*)qp, M, QK_DIM, DIM);
    // KV = context @ Wkv
    gemm_mma<<<dim3(KVW / 128, M / 128), 256, GEMM_SMEM>>>(
        (const __nv_bfloat16*)ch, (const __nv_bfloat16*)cl,
        (const __nv_bfloat16*)wkh, (const __nv_bfloat16*)wkl,
        (float*)kvp, M, KVW, DIM);

    attn64<<<dim3(NSEQ / 64, HEADS, BATCH), 256>>>((const float*)qp, (const float*)kvp, out);
}

// round 5
// speedup vs baseline: 3.4158x; 2.5881x over previous
#include <cuda_runtime.h>
#include <cuda_bf16.h>
#include <cstdint>

#define BATCH   4
#define NSEQ    2048
#define DIM     1024
#define QK_DIM  1024
#define V_DIM   1024
#define HEADS   16
#define DHEAD   64
#define KVW     (QK_DIM + V_DIM)   // 2048
#define MROWS   (BATCH * NSEQ)     // 8192

// ---------------- scratch (__device__ globals; no allocs allowed) ----------
__device__ float g_q [ (size_t)MROWS * QK_DIM ];
__device__ float g_kv[ (size_t)MROWS * KVW    ];
__device__ __nv_bfloat16 g_xh[ (size_t)MROWS * DIM ];
__device__ __nv_bfloat16 g_xl[ (size_t)MROWS * DIM ];
__device__ __nv_bfloat16 g_ch[ (size_t)MROWS * DIM ];
__device__ __nv_bfloat16 g_cl[ (size_t)MROWS * DIM ];
__device__ __nv_bfloat16 g_wqh[ (size_t)QK_DIM * DIM ];   // [N,K]
__device__ __nv_bfloat16 g_wql[ (size_t)QK_DIM * DIM ];
__device__ __nv_bfloat16 g_wkh[ (size_t)KVW * DIM ];      // [N,K]
__device__ __nv_bfloat16 g_wkl[ (size_t)KVW * DIM ];
// attention operands, per-head layouts
__device__ __nv_bfloat16 g_qh [ (size_t)MROWS * QK_DIM ];   // [bh][i][d]
__device__ __nv_bfloat16 g_ql [ (size_t)MROWS * QK_DIM ];
__device__ __nv_bfloat16 g_kh [ (size_t)MROWS * QK_DIM ];   // [bh][j][d]
__device__ __nv_bfloat16 g_kl [ (size_t)MROWS * QK_DIM ];
__device__ __nv_bfloat16 g_vth[ (size_t)MROWS * V_DIM  ];   // [bh][d][j]
__device__ __nv_bfloat16 g_vtl[ (size_t)MROWS * V_DIM  ];

// ---------------- small PTX helpers (baseline sm_80+, no 'a' features) -----
__device__ __forceinline__ uint32_t smem_u32(const void* p) {
    uint32_t a;
    asm("{ .reg .u64 t; cvta.to.shared.u64 t, %1; cvt.u32.u64 %0, t; }"
        : "=r"(a) : "l"(p));
    return a;
}
__device__ __forceinline__ void cp_async16(uint32_t sdst, const void* gsrc) {
    asm volatile("cp.async.cg.shared.global [%0], [%1], 16;"
                 :: "r"(sdst), "l"(gsrc) : "memory");
}
#define CP_COMMIT() asm volatile("cp.async.commit_group;" ::: "memory")
#define CP_WAIT(N)  asm volatile("cp.async.wait_group %0;" :: "n"(N) : "memory")

__device__ __forceinline__ void ldsm4(uint32_t* r, uint32_t addr) {
    asm volatile("ldmatrix.sync.aligned.m8n8.x4.shared.b16 {%0,%1,%2,%3}, [%4];"
                 : "=r"(r[0]), "=r"(r[1]), "=r"(r[2]), "=r"(r[3]) : "r"(addr));
}
__device__ __forceinline__ void mma16816(float* c, const uint32_t* a,
                                         uint32_t b0, uint32_t b1) {
    asm volatile(
        "mma.sync.aligned.m16n8k16.row.col.f32.bf16.bf16.f32 "
        "{%0,%1,%2,%3}, {%4,%5,%6,%7}, {%8,%9}, {%0,%1,%2,%3};"
        : "+f"(c[0]), "+f"(c[1]), "+f"(c[2]), "+f"(c[3])
        : "r"(a[0]), "r"(a[1]), "r"(a[2]), "r"(a[3]), "r"(b0), "r"(b1));
}

// ---------------- split helpers ---------------------------------------------
__device__ __forceinline__ void split1(float x, __nv_bfloat16& h, __nv_bfloat16& l) {
    h = __float2bfloat16(x);
    l = __float2bfloat16(x - __bfloat162float(h));
}
__device__ __forceinline__ void split_pk(float a, float b, uint32_t& hp, uint32_t& lp) {
    __nv_bfloat16 ha = __float2bfloat16(a), hb = __float2bfloat16(b);
    float ra = a - __bfloat162float(ha);
    float rb = b - __bfloat162float(hb);
    hp = (uint32_t)__bfloat16_as_ushort(ha) |
         ((uint32_t)__bfloat16_as_ushort(hb) << 16);
    lp = (uint32_t)__bfloat16_as_ushort(__float2bfloat16(ra)) |
         ((uint32_t)__bfloat16_as_ushort(__float2bfloat16(rb)) << 16);
}

__global__ __launch_bounds__(256) void asplit(const float* __restrict__ X,
                                              __nv_bfloat16* __restrict__ hi,
                                              __nv_bfloat16* __restrict__ lo,
                                              int n) {
    int i = (blockIdx.x * 256 + threadIdx.x) * 4;
    if (i >= n) return;
    float4 v = *reinterpret_cast<const float4*>(X + i);
    __nv_bfloat16 h[4], l[4];
    split1(v.x, h[0], l[0]); split1(v.y, h[1], l[1]);
    split1(v.z, h[2], l[2]); split1(v.w, h[3], l[3]);
    *reinterpret_cast<uint2*>(hi + i) = *reinterpret_cast<uint2*>(h);
    *reinterpret_cast<uint2*>(lo + i) = *reinterpret_cast<uint2*>(l);
}

// W [K,N] f32 -> hi/lo [N,K] bf16 (transpose + split)
__global__ void wsplit(const float* __restrict__ W,
                       __nv_bfloat16* __restrict__ hi,
                       __nv_bfloat16* __restrict__ lo,
                       int Kd, int Nd) {
    __shared__ float t[32][33];
    int n0 = blockIdx.x * 32, k0 = blockIdx.y * 32;
    int tx = threadIdx.x, ty = threadIdx.y;    // (32, 8)
#pragma unroll
    for (int i = 0; i < 32; i += 8)
        t[ty + i][tx] = W[(size_t)(k0 + ty + i) * Nd + n0 + tx];
    __syncthreads();
#pragma unroll
    for (int i = 0; i < 32; i += 8) {
        float v = t[tx][ty + i];
        __nv_bfloat16 h, l; split1(v, h, l);
        hi[(size_t)(n0 + ty + i) * Kd + k0 + tx] = h;
        lo[(size_t)(n0 + ty + i) * Kd + k0 + tx] = l;
    }
}

// per-head extraction: src [8192][srcld] f32 -> dst [bh][row][64] bf16 hi/lo
__global__ __launch_bounds__(256) void hsplit(const float* __restrict__ src,
                                              __nv_bfloat16* __restrict__ hi,
                                              __nv_bfloat16* __restrict__ lo,
                                              int srcld, int coloff, float scale) {
    int t  = blockIdx.x * 256 + threadIdx.x;   // 2,097,152 threads
    int d4 = t & 15;                           // 4-elem chunk along d
    int i  = (t >> 4) & (NSEQ - 1);
    int bh = t >> 15;                          // 0..63
    int b  = bh >> 4, h = bh & 15;
    const float* sp = src + ((size_t)(b * NSEQ + i)) * srcld + coloff + h * DHEAD + d4 * 4;
    float4 v = *reinterpret_cast<const float4*>(sp);
    __nv_bfloat16 hh[4], ll[4];
    split1(v.x * scale, hh[0], ll[0]); split1(v.y * scale, hh[1], ll[1]);
    split1(v.z * scale, hh[2], ll[2]); split1(v.w * scale, hh[3], ll[3]);
    size_t o = ((size_t)bh * NSEQ + i) * DHEAD + d4 * 4;
    *reinterpret_cast<uint2*>(hi + o) = *reinterpret_cast<uint2*>(hh);
    *reinterpret_cast<uint2*>(lo + o) = *reinterpret_cast<uint2*>(ll);
}

// V transpose+split: g_kv[b][j][1024 + h*64 + d] -> vt [bh][d][j]
__global__ void vtsplit(const float* __restrict__ kvsrc,
                        __nv_bfloat16* __restrict__ hi,
                        __nv_bfloat16* __restrict__ lo) {
    __shared__ float tbuf[32][33];
    int j0 = blockIdx.x * 32, d0 = blockIdx.y * 32;
    int bh = blockIdx.z; int b = bh >> 4, h = bh & 15;
    const float* sp = kvsrc + (size_t)b * NSEQ * KVW + QK_DIM + h * DHEAD;
    int tx = threadIdx.x, ty = threadIdx.y;    // (32,8)
#pragma unroll
    for (int i = 0; i < 32; i += 8)
        tbuf[ty + i][tx] = sp[(size_t)(j0 + ty + i) * KVW + d0 + tx];
    __syncthreads();
#pragma unroll
    for (int i = 0; i < 32; i += 8) {
        float v = tbuf[tx][ty + i];
        __nv_bfloat16 hh, ll; split1(v, hh, ll);
        size_t o = ((size_t)bh * DHEAD + d0 + ty + i) * NSEQ + j0 + tx;
        hi[o] = hh; lo[o] = ll;
    }
}

// ---------------- HMMA GEMM (unchanged from round 4) ------------------------
#define BK 64
#define TILE_B (128 * 128)
#define STAGE_B (4 * TILE_B)
#define GEMM_SMEM (2 * STAGE_B)

__global__ __launch_bounds__(256, 1) void gemm_mma(
        const __nv_bfloat16* __restrict__ Ahi,
        const __nv_bfloat16* __restrict__ Alo,
        const __nv_bfloat16* __restrict__ Bhi,
        const __nv_bfloat16* __restrict__ Blo,
        float* __restrict__ C, int M, int N, int K) {
    extern __shared__ __align__(1024) char dsm[];
    const uint32_t sbase = smem_u32(dsm);

    const int tid  = threadIdx.x;
    const int wid  = tid >> 5;
    const int lane = tid & 31;
    const int wm   = wid & 3;
    const int wn   = wid >> 2;
    const int rowBase = blockIdx.y * 128;
    const int colBase = blockIdx.x * 128;

    const __nv_bfloat16* gsrc[4] = {
        Ahi + (size_t)rowBase * K, Alo + (size_t)rowBase * K,
        Bhi + (size_t)colBase * K, Blo + (size_t)colBase * K };

    auto stage = [&](int kt, int buf) {
        const uint32_t sb = sbase + buf * STAGE_B;
#pragma unroll
        for (int t = 0; t < 4; t++) {
            const __nv_bfloat16* gp = gsrc[t] + kt * BK;
            const uint32_t stile = sb + t * TILE_B;
#pragma unroll
            for (int i = 0; i < 4; i++) {
                int idx = tid + i * 256;
                int r   = idx >> 3;
                int c   = idx & 7;
                uint32_t so = (uint32_t)(r * 128 + ((c * 16) ^ ((r & 7) << 4)));
                cp_async16(stile + so, gp + (size_t)r * K + c * 8);
            }
        }
        CP_COMMIT();
    };

    int arow[2], axor[2];
#pragma unroll
    for (int mt = 0; mt < 2; mt++) {
        int row = wm * 32 + mt * 16 + (lane & 15);
        arow[mt] = row * 128;
        axor[mt] = (row & 7) << 4;
    }
    const int acolh = (lane >> 4) * 16;
    int brow[4], bxor[4];
#pragma unroll
    for (int nn = 0; nn < 4; nn++) {
        int row = wn * 64 + nn * 16 + (lane & 7) + ((lane >> 4) << 3);
        brow[nn] = row * 128;
        bxor[nn] = (row & 7) << 4;
    }
    const int bcolh = ((lane >> 3) & 1) * 16;

    float acc[2][8][4];
#pragma unroll
    for (int mt = 0; mt < 2; mt++)
#pragma unroll
        for (int nt = 0; nt < 8; nt++)
#pragma unroll
            for (int i = 0; i < 4; i++) acc[mt][nt][i] = 0.f;

    const int KT = K / BK;
    stage(0, 0);

    for (int kt = 0; kt < KT; kt++) {
        if (kt + 1 < KT) { stage(kt + 1, (kt + 1) & 1); CP_WAIT(1); }
        else             { CP_WAIT(0); }
        __syncthreads();

        const uint32_t sb   = sbase + (kt & 1) * STAGE_B;
        const uint32_t sAhi = sb;
        const uint32_t sAlo = sb + TILE_B;
        const uint32_t sBhi = sb + 2 * TILE_B;
        const uint32_t sBlo = sb + 3 * TILE_B;

#pragma unroll
        for (int kk = 0; kk < 4; kk++) {
            const int kb = kk * 32;
            uint32_t ah[2][4], al[2][4], bh[4][4], bl[4][4];
#pragma unroll
            for (int mt = 0; mt < 2; mt++) {
                uint32_t off = (uint32_t)(arow[mt] + ((kb + acolh) ^ axor[mt]));
                ldsm4(ah[mt], sAhi + off);
                ldsm4(al[mt], sAlo + off);
            }
#pragma unroll
            for (int nn = 0; nn < 4; nn++) {
                uint32_t off = (uint32_t)(brow[nn] + ((kb + bcolh) ^ bxor[nn]));
                ldsm4(bh[nn], sBhi + off);
                ldsm4(bl[nn], sBlo + off);
            }
#pragma unroll
            for (int mt = 0; mt < 2; mt++)
#pragma unroll
                for (int nt = 0; nt < 8; nt++) {
                    const int nn = nt >> 1, hf = (nt & 1) * 2;
                    mma16816(acc[mt][nt], ah[mt], bh[nn][hf], bh[nn][hf + 1]);
                    mma16816(acc[mt][nt], ah[mt], bl[nn][hf], bl[nn][hf + 1]);
                    mma16816(acc[mt][nt], al[mt], bh[nn][hf], bh[nn][hf + 1]);
                }
        }
        __syncthreads();
    }

    const int g   = lane >> 2;
    const int tig = lane & 3;
#pragma unroll
    for (int mt = 0; mt < 2; mt++) {
        const int row0 = rowBase + wm * 32 + mt * 16 + g;
#pragma unroll
        for (int nt = 0; nt < 8; nt++) {
            const int col = colBase + wn * 64 + nt * 8 + tig * 2;
            *reinterpret_cast<float2*>(&C[(size_t)row0 * N + col]) =
                make_float2(acc[mt][nt][0], acc[mt][nt][1]);
            *reinterpret_cast<float2*>(&C[(size_t)(row0 + 8) * N + col]) =
                make_float2(acc[mt][nt][2], acc[mt][nt][3]);
        }
    }
}

// ---------------- HMMA flash attention --------------------------------------
// CTA: 128 q rows x one (b,h). 8 warps x 16 rows. KV tiles of 64, double buf.
// Q/K/V bf16 hi/lo; P split in registers; 3-product MMA both phases.
#define ABQ 128
#define ABJ 64
#define QT_B (ABQ * 128)            // 16KB per Q tile (hi or lo)
#define KT_B (ABJ * 128)            // 8KB per K/V tile
#define AST_B (4 * KT_B)            // Kh,Kl,Vh,Vl = 32KB per stage
#define ATTN_SMEM (2 * QT_B + 2 * AST_B)   // 96KB

__global__ __launch_bounds__(256, 1) void attn_mma(
        const __nv_bfloat16* __restrict__ Qh, const __nv_bfloat16* __restrict__ Ql,
        const __nv_bfloat16* __restrict__ Kh, const __nv_bfloat16* __restrict__ Kl,
        const __nv_bfloat16* __restrict__ Vth, const __nv_bfloat16* __restrict__ Vtl,
        float* __restrict__ out) {
    extern __shared__ __align__(1024) char dsm[];
    const uint32_t base = smem_u32(dsm);
    const uint32_t sQh = base, sQl = base + QT_B;

    const int tid  = threadIdx.x;
    const int wid  = tid >> 5;
    const int lane = tid & 31;
    const int qt = blockIdx.x, h = blockIdx.y, b = blockIdx.z;
    const int bh = b * HEADS + h;

    const __nv_bfloat16* gQh = Qh + ((size_t)bh * NSEQ + qt * ABQ) * DHEAD;
    const __nv_bfloat16* gQl = Ql + ((size_t)bh * NSEQ + qt * ABQ) * DHEAD;
    const __nv_bfloat16* gKh = Kh + (size_t)bh * NSEQ * DHEAD;
    const __nv_bfloat16* gKl = Kl + (size_t)bh * NSEQ * DHEAD;
    const __nv_bfloat16* gVh = Vth + (size_t)bh * DHEAD * NSEQ;
    const __nv_bfloat16* gVl = Vtl + (size_t)bh * DHEAD * NSEQ;

    // stage Q (group 0)
    {
        const __nv_bfloat16* gq[2] = { gQh, gQl };
#pragma unroll
        for (int t = 0; t < 2; t++) {
            uint32_t st = (t == 0) ? sQh : sQl;
#pragma unroll
            for (int i = 0; i < 4; i++) {
                int idx = tid + i * 256;      // 0..1023
                int r = idx >> 3, c = idx & 7;
                uint32_t so = (uint32_t)(r * 128 + ((c * 16) ^ ((r & 7) << 4)));
                cp_async16(st + so, gq[t] + (size_t)r * DHEAD + c * 8);
            }
        }
        CP_COMMIT();
    }

    auto stageKV = [&](int jt, int buf) {
        const uint32_t sb = base + 2 * QT_B + buf * AST_B;
        const __nv_bfloat16* gk[2] = { gKh + (size_t)jt * ABJ * DHEAD,
                                       gKl + (size_t)jt * ABJ * DHEAD };
        const __nv_bfloat16* gv[2] = { gVh + (size_t)jt * ABJ,
                                       gVl + (size_t)jt * ABJ };
#pragma unroll
        for (int t = 0; t < 2; t++) {
            const uint32_t sK = sb + t * KT_B;
            const uint32_t sV = sb + (2 + t) * KT_B;
#pragma unroll
            for (int i = 0; i < 2; i++) {
                int idx = tid + i * 256;      // 0..511
                int r = idx >> 3, c = idx & 7;
                uint32_t so = (uint32_t)(r * 128 + ((c * 16) ^ ((r & 7) << 4)));
                cp_async16(sK + so, gk[t] + (size_t)r * DHEAD + c * 8);
                cp_async16(sV + so, gv[t] + (size_t)r * NSEQ + c * 8);
            }
        }
        CP_COMMIT();
    };

    // per-lane fragment addressing
    const int qrow = wid * 16 + (lane & 15);
    const int arow = qrow * 128;
    const int axor = (qrow & 7) << 4;
    const int acolh = (lane >> 4) * 16;
    int brow[4], bxor[4];
#pragma unroll
    for (int nn = 0; nn < 4; nn++) {
        int row = nn * 16 + (lane & 7) + ((lane >> 4) << 3);
        brow[nn] = row * 128;
        bxor[nn] = (row & 7) << 4;
    }
    const int bcolh = ((lane >> 3) & 1) * 16;
    const int g = lane >> 2, tig = lane & 3;

    float ao[8][4];
#pragma unroll
    for (int nt = 0; nt < 8; nt++)
#pragma unroll
        for (int i = 0; i < 4; i++) ao[nt][i] = 0.f;
    float m0 = -1e30f, m1 = -1e30f, l0 = 0.f, l1 = 0.f;

    stageKV(0, 0);

    const int JT = NSEQ / ABJ;     // 32
    for (int jt = 0; jt < JT; jt++) {
        if (jt + 1 < JT) { stageKV(jt + 1, (jt + 1) & 1); CP_WAIT(1); }
        else             { CP_WAIT(0); }
        __syncthreads();

        const uint32_t sb  = base + 2 * QT_B + (jt & 1) * AST_B;
        const uint32_t sKh = sb, sKl = sb + KT_B;
        const uint32_t sVh = sb + 2 * KT_B, sVl = sb + 3 * KT_B;

        // --- S = Q K^T (3-product) ---
        float as[8][4];
#pragma unroll
        for (int nt = 0; nt < 8; nt++)
#pragma unroll
            for (int i = 0; i < 4; i++) as[nt][i] = 0.f;
#pragma unroll
        for (int kk = 0; kk < 4; kk++) {
            const int kb = kk * 32;
            uint32_t qh_[4], ql_[4], kh_[4][4], kl_[4][4];
            {
                uint32_t off = (uint32_t)(arow + ((kb + acolh) ^ axor));
                ldsm4(qh_, sQh + off);
                ldsm4(ql_, sQl + off);
            }
#pragma unroll
            for (int nn = 0; nn < 4; nn++) {
                uint32_t off = (uint32_t)(brow[nn] + ((kb + bcolh) ^ bxor[nn]));
                ldsm4(kh_[nn], sKh + off);
                ldsm4(kl_[nn], sKl + off);
            }
#pragma unroll
            for (int nt = 0; nt < 8; nt++) {
                const int nn = nt >> 1, hf = (nt & 1) * 2;
                mma16816(as[nt], qh_, kh_[nn][hf], kh_[nn][hf + 1]);
                mma16816(as[nt], qh_, kl_[nn][hf], kl_[nn][hf + 1]);
                mma16816(as[nt], ql_, kh_[nn][hf], kh_[nn][hf + 1]);
            }
        }

        // --- online softmax (rows g and g+8 of this warp's 16) ---
        float smax0 = -1e30f, smax1 = -1e30f;
#pragma unroll
        for (int nt = 0; nt < 8; nt++) {
            smax0 = fmaxf(smax0, fmaxf(as[nt][0], as[nt][1]));
            smax1 = fmaxf(smax1, fmaxf(as[nt][2], as[nt][3]));
        }
#pragma unroll
        for (int o = 1; o < 4; o <<= 1) {
            smax0 = fmaxf(smax0, __shfl_xor_sync(0xffffffffu, smax0, o));
            smax1 = fmaxf(smax1, __shfl_xor_sync(0xffffffffu, smax1, o));
        }
        const float mn0 = fmaxf(m0, smax0);
        const float mn1 = fmaxf(m1, smax1);
        const float al0 = __expf(m0 - mn0);
        const float al1 = __expf(m1 - mn1);
        m0 = mn0; m1 = mn1;
        float ls0 = 0.f, ls1 = 0.f;
#pragma unroll
        for (int nt = 0; nt < 8; nt++) {
            as[nt][0] = __expf(as[nt][0] - mn0);
            as[nt][1] = __expf(as[nt][1] - mn0);
            as[nt][2] = __expf(as[nt][2] - mn1);
            as[nt][3] = __expf(as[nt][3] - mn1);
            ls0 += as[nt][0] + as[nt][1];
            ls1 += as[nt][2] + as[nt][3];
        }
#pragma unroll
        for (int o = 1; o < 4; o <<= 1) {
            ls0 += __shfl_xor_sync(0xffffffffu, ls0, o);
            ls1 += __shfl_xor_sync(0xffffffffu, ls1, o);
        }
        l0 = l0 * al0 + ls0;
        l1 = l1 * al1 + ls1;
#pragma unroll
        for (int nt = 0; nt < 8; nt++) {
            ao[nt][0] *= al0; ao[nt][1] *= al0;
            ao[nt][2] *= al1; ao[nt][3] *= al1;
        }

        // --- O += P V (P split in registers, 3-product) ---
#pragma unroll
        for (int kk = 0; kk < 4; kk++) {
            const int kb = kk * 32;
            uint32_t ph[4], pl[4];
            split_pk(as[2 * kk][0],     as[2 * kk][1],     ph[0], pl[0]);
            split_pk(as[2 * kk][2],     as[2 * kk][3],     ph[1], pl[1]);
            split_pk(as[2 * kk + 1][0], as[2 * kk + 1][1], ph[2], pl[2]);
            split_pk(as[2 * kk + 1][2], as[2 * kk + 1][3], ph[3], pl[3]);
            uint32_t vh_[4][4], vl_[4][4];
#pragma unroll
            for (int nn = 0; nn < 4; nn++) {
                uint32_t off = (uint32_t)(brow[nn] + ((kb + bcolh) ^ bxor[nn]));
                ldsm4(vh_[nn], sVh + off);
                ldsm4(vl_[nn], sVl + off);
            }
#pragma unroll
            for (int nt = 0; nt < 8; nt++) {
                const int nn = nt >> 1, hf = (nt & 1) * 2;
                mma16816(ao[nt], ph, vh_[nn][hf], vh_[nn][hf + 1]);
                mma16816(ao[nt], ph, vl_[nn][hf], vl_[nn][hf + 1]);
                mma16816(ao[nt], pl, vh_[nn][hf], vh_[nn][hf + 1]);
            }
        }
        __syncthreads();
    }

    // epilogue
    const float inv0 = 1.f / l0, inv1 = 1.f / l1;
    const int i0 = qt * ABQ + wid * 16 + g;
#pragma unroll
    for (int nt = 0; nt < 8; nt++) {
        const int col = h * DHEAD + nt * 8 + tig * 2;
        *reinterpret_cast<float2*>(&out[((size_t)(b * NSEQ + i0)) * (HEADS * DHEAD) + col]) =
            make_float2(ao[nt][0] * inv0, ao[nt][1] * inv0);
        *reinterpret_cast<float2*>(&out[((size_t)(b * NSEQ + i0 + 8)) * (HEADS * DHEAD) + col]) =
            make_float2(ao[nt][2] * inv1, ao[nt][3] * inv1);
    }
}

// ---------------------------------------------------------------------------
extern "C" void kernel_launch(void* const* d_in, const int* in_sizes, int n_in,
                              void* d_out, int out_size) {
    const float* x   = (const float*)d_in[0];
    const float* ctx = (const float*)d_in[1];
    const float* Wq  = (const float*)d_in[2];
    const float* Wkv = (const float*)d_in[3];
    if (n_in >= 4 && in_sizes[2] == QK_DIM * KVW && in_sizes[3] == DIM * QK_DIM) {
        const float* t = Wq; Wq = Wkv; Wkv = t;
    }
    float* out = (float*)d_out;

    void *qp, *kvp, *xh, *xl, *ch, *cl, *wqh, *wql, *wkh, *wkl;
    void *qhh, *qll, *khh, *kll, *vth, *vtl;
    cudaGetSymbolAddress(&qp,  g_q);   cudaGetSymbolAddress(&kvp, g_kv);
    cudaGetSymbolAddress(&xh,  g_xh);  cudaGetSymbolAddress(&xl,  g_xl);
    cudaGetSymbolAddress(&ch,  g_ch);  cudaGetSymbolAddress(&cl,  g_cl);
    cudaGetSymbolAddress(&wqh, g_wqh); cudaGetSymbolAddress(&wql, g_wql);
    cudaGetSymbolAddress(&wkh, g_wkh); cudaGetSymbolAddress(&wkl, g_wkl);
    cudaGetSymbolAddress(&qhh, g_qh);  cudaGetSymbolAddress(&qll, g_ql);
    cudaGetSymbolAddress(&khh, g_kh);  cudaGetSymbolAddress(&kll, g_kl);
    cudaGetSymbolAddress(&vth, g_vth); cudaGetSymbolAddress(&vtl, g_vtl);

    cudaFuncSetAttribute(gemm_mma, cudaFuncAttributeMaxDynamicSharedMemorySize,
                         GEMM_SMEM);
    cudaFuncSetAttribute(attn_mma, cudaFuncAttributeMaxDynamicSharedMemorySize,
                         ATTN_SMEM);

    const int M = MROWS;
    const int nAct = M * DIM;

    asplit<<<nAct / (256 * 4), 256>>>(x,   (__nv_bfloat16*)xh, (__nv_bfloat16*)xl, nAct);
    asplit<<<nAct / (256 * 4), 256>>>(ctx, (__nv_bfloat16*)ch, (__nv_bfloat16*)cl, nAct);
    wsplit<<<dim3(QK_DIM / 32, DIM / 32), dim3(32, 8)>>>(
        Wq, (__nv_bfloat16*)wqh, (__nv_bfloat16*)wql, DIM, QK_DIM);
    wsplit<<<dim3(KVW / 32, DIM / 32), dim3(32, 8)>>>(
        Wkv, (__nv_bfloat16*)wkh, (__nv_bfloat16*)wkl, DIM, KVW);

    gemm_mma<<<dim3(QK_DIM / 128, M / 128), 256, GEMM_SMEM>>>(
        (const __nv_bfloat16*)xh, (const __nv_bfloat16*)xl,
        (const __nv_bfloat16*)wqh, (const __nv_bfloat16*)wql,
        (float*)qp, M, QK_DIM, DIM);
    gemm_mma<<<dim3(KVW / 128, M / 128), 256, GEMM_SMEM>>>(
        (const __nv_bfloat16*)ch, (const __nv_bfloat16*)cl,
        (const __nv_bfloat16*)wkh, (const __nv_bfloat16*)wkl,
        (float*)kvp, M, KVW, DIM);

    // per-head attention operands (scale 1/8 folded into Q; exact pow2)
    const int nThreads = 64 * NSEQ * 16;   // bh * i * d4
    hsplit<<<nThreads / 256, 256>>>((const float*)qp,
        (__nv_bfloat16*)qhh, (__nv_bfloat16*)qll, QK_DIM, 0, 0.125f);
    hsplit<<<nThreads / 256, 256>>>((const float*)kvp,
        (__nv_bfloat16*)khh, (__nv_bfloat16*)kll, KVW, 0, 1.0f);
    vtsplit<<<dim3(NSEQ / 32, DHEAD / 32, 64), dim3(32, 8)>>>(
        (const float*)kvp, (__nv_bfloat16*)vth, (__nv_bfloat16*)vtl);

    attn_mma<<<dim3(NSEQ / ABQ, HEADS, BATCH), 256, ATTN_SMEM>>>(
        (const __nv_bfloat16*)qhh, (const __nv_bfloat16*)qll,
        (const __nv_bfloat16*)khh, (const __nv_bfloat16*)kll,
        (const __nv_bfloat16*)vth, (const __nv_bfloat16*)vtl, out);
}